// round 16
// baseline (speedup 1.0000x reference)
#include <cuda_runtime.h>
#include <cuda_fp16.h>
#include <cstdint>
#include <math.h>

// Problem dims (fixed by the dataset)
#define Bn 16384
#define Dn 4096
#define Hh 32
#define HDh 128
#define EPSf 1e-5f

// ---- fp16 mma.sync GEMM tiling: 256x128 CTA tile, warp tile 64x64, occ 1 ----
#define BM 256
#define BN 128
#define BKh 64                 // K elements (fp16) per stage => 128 bytes/row
#define STG 4
#define ROWB 128               // bytes per smem row
#define AST (BM * ROWB)        // 32768
#define BST (BN * ROWB)        // 16384
#define STAGE_B (AST + BST)    // 49152
#define SMEMB (STG * STAGE_B + 1024)  // 197632
#define NKT (4096 / BKh)       // 64

// ---------------- scratch (static device allocations; no cudaMalloc) --------
__device__ __half d_g16[(size_t)Bn * Dn];
__device__ __half d_h16[(size_t)Bn * Dn];
__device__ __half d_qkv16[(size_t)Bn * 3 * Dn];
__device__ __half d_w16[4][(size_t)Dn * Dn];   // wq, wk, wv (contiguous = QKV), wo
__device__ float d_bqkv[3 * Dn];
__device__ float d_xm[Bn];
__device__ float d_gx[Bn];
__device__ float d_gy[Dn];
__device__ float d_part[64 * Dn];

// ---------------- helpers -----------------------------------------------------
__device__ __forceinline__ uint32_t smem_u32(const void* p) {
    uint32_t a;
    asm("{ .reg .u64 t; cvta.to.shared.u64 t, %1; cvt.u32.u64 %0, t; }" : "=r"(a) : "l"(p));
    return a;
}
__device__ __forceinline__ void cp_async16(uint32_t saddr, const void* gptr) {
    asm volatile("cp.async.cg.shared.global [%0], [%1], 16;\n" ::"r"(saddr), "l"(gptr));
}
#define LDSM_X4(r, addr)                                                         \
    asm volatile("ldmatrix.sync.aligned.m8n8.x4.shared.b16 {%0,%1,%2,%3}, [%4];" \
                 : "=r"((r)[0]), "=r"((r)[1]), "=r"((r)[2]), "=r"((r)[3])        \
                 : "r"(addr))
__device__ __forceinline__ void mma_h(float* c, const uint32_t* a, uint32_t b0, uint32_t b1) {
    asm volatile(
        "mma.sync.aligned.m16n8k16.row.col.f32.f16.f16.f32 "
        "{%0,%1,%2,%3}, {%4,%5,%6,%7}, {%8,%9}, {%0,%1,%2,%3};\n"
        : "+f"(c[0]), "+f"(c[1]), "+f"(c[2]), "+f"(c[3])
        : "r"(a[0]), "r"(a[1]), "r"(a[2]), "r"(a[3]), "r"(b0), "r"(b1));
}
__device__ __forceinline__ float warp_sum(float v) {
#pragma unroll
    for (int o = 16; o > 0; o >>= 1) v += __shfl_down_sync(0xffffffffu, v, o);
    return v;
}

// ---- L0: rowmean (blocks 0..16383, float4) + colpart (blocks 16384..) -------
__global__ void rowcol_kernel(const float* __restrict__ x, float* __restrict__ xm,
                              float* __restrict__ part) {
    __shared__ float sred[4];
    int t = threadIdx.x;
    if (blockIdx.x < Bn) {
        int b = blockIdx.x;
        const float4* xr = (const float4*)(x + (size_t)b * Dn);
        float s = 0.f;
#pragma unroll
        for (int i = 0; i < 8; i++) {
            float4 v = xr[t + i * 128];
            s += (v.x + v.y) + (v.z + v.w);
        }
        s = warp_sum(s);
        if ((t & 31) == 0) sred[t >> 5] = s;
        __syncthreads();
        if (t == 0) xm[b] = (sred[0] + sred[1] + sred[2] + sred[3]) * (1.0f / Dn);
    } else {
        int j = blockIdx.x - Bn;       // 0..2047
        int c = (j & 31) * 128 + t;    // column
        int r0 = (j >> 5) * 256;       // row chunk
        float s = 0.f;
        for (int i = 0; i < 256; i++) s += x[(size_t)(r0 + i) * Dn + c];
        part[(size_t)(j >> 5) * Dn + c] = s;
    }
}

// ---- L1: block 0 = colmeans + stats + gate tables; blocks 1..12 = QKV bias --
__global__ __launch_bounds__(1024) void statsall_kernel(
    const float* __restrict__ part, const float* __restrict__ xm,
    const float* __restrict__ wxp, const float* __restrict__ wyp,
    const float* __restrict__ bq, const float* __restrict__ bk,
    const float* __restrict__ bv,
    float* __restrict__ gx, float* __restrict__ gy, float* __restrict__ bqkv) {
    int t = threadIdx.x;
    if (blockIdx.x > 0) {
        int i = (blockIdx.x - 1) * 1024 + t;   // 0..12287
        float v = (i < Dn) ? bq[i] : (i < 2 * Dn) ? bk[i - Dn] : bv[i - 2 * Dn];
        bqkv[i] = v;
        return;
    }
    __shared__ float sA[32], sB[32], sC[32], sD[32];
    __shared__ float sbc[4];
    float cm[4];
    float ys = 0.f, yss = 0.f;
#pragma unroll
    for (int j = 0; j < 4; j++) {
        int c = t + j * 1024;
        float s = 0.f;
#pragma unroll 1
        for (int b = 0; b < 64; b++) s += part[(size_t)b * Dn + c];
        float m = s * (1.0f / Bn);
        cm[j] = m;
        ys += m;
        yss += m * m;
    }
    float xs = 0.f, xss = 0.f;
    for (int i = t; i < Bn; i += 1024) {
        float u = xm[i];
        xs += u;
        xss += u * u;
    }
    xs = warp_sum(xs);
    xss = warp_sum(xss);
    ys = warp_sum(ys);
    yss = warp_sum(yss);
    if ((t & 31) == 0) { sA[t >> 5] = xs; sB[t >> 5] = xss; sC[t >> 5] = ys; sD[t >> 5] = yss; }
    __syncthreads();
    if (t == 0) {
        float XS = 0.f, XSS = 0.f, YS = 0.f, YSS = 0.f;
        for (int j = 0; j < 32; j++) { XS += sA[j]; XSS += sB[j]; YS += sC[j]; YSS += sD[j]; }
        float xmean = XS * (1.0f / Bn);
        float xvar = XSS * (1.0f / Bn) - xmean * xmean;
        float wxv = *wxp;
        sbc[0] = xmean;
        sbc[1] = sqrtf(wxv * wxv * xvar + EPSf) + EPSf;
        float ymean = YS * (1.0f / Dn);
        float yvar = YSS * (1.0f / Dn) - ymean * ymean;
        float wyv = *wyp;
        sbc[2] = ymean;
        sbc[3] = sqrtf(wyv * wyv * yvar + EPSf) + EPSf;
    }
    __syncthreads();
    const float xmean = sbc[0], xden = sbc[1], ymean = sbc[2], yden = sbc[3];
    const float wxv = *wxp, wyv = *wyp;
#pragma unroll
    for (int j = 0; j < 4; j++) {
        int c = t + j * 1024;
        float z = wyv * (cm[j] - ymean) / yden;
        gy[c] = 1.0f / (1.0f + expf(-z));
    }
    for (int i = t; i < Bn; i += 1024) {
        float z = wxv * (xm[i] - xmean) / xden;
        gx[i] = 1.0f / (1.0f + expf(-z));
    }
}

// ---- L2: fused gated-multiply (blocks < GMB, table lookups) + weight f2h ----
#define GMB 65536  // gmul blocks: 16M float4 / 256
__global__ void mega_kernel(const float* __restrict__ x, const float* __restrict__ gx,
                            const float* __restrict__ gy, __half* __restrict__ g16,
                            const float4* __restrict__ w0, const float4* __restrict__ w1,
                            const float4* __restrict__ w2, const float4* __restrict__ w3,
                            __half2* __restrict__ wdst) {
    if (blockIdx.x < GMB) {
        size_t i4 = (size_t)blockIdx.x * 256 + threadIdx.x;
        int b = (int)(i4 >> 10);
        int d = (int)((i4 & 1023) << 2);
        float gxv = gx[b];
        float4 gyv = *(const float4*)(gy + d);
        float4 xv = *(const float4*)(x + ((size_t)b << 12) + d);
        float4 gv;
        gv.x = xv.x * gxv * gyv.x;
        gv.y = xv.y * gxv * gyv.y;
        gv.z = xv.z * gxv * gyv.z;
        gv.w = xv.w * gxv * gyv.w;
        *(__half2*)(g16 + ((size_t)b << 12) + d) = __floats2half2_rn(gv.x, gv.y);
        *(__half2*)(g16 + ((size_t)b << 12) + d + 2) = __floats2half2_rn(gv.z, gv.w);
    } else {
        const float4* srcs[4] = {w0, w1, w2, w3};
        int j = blockIdx.x - GMB;          // 0..65535
        int wsel = j >> 14;                // 16384 blocks per weight
        size_t i = (size_t)(j & 16383) * 256 + threadIdx.x;
        float4 v = srcs[wsel][i];
        __half2* d = wdst + (size_t)wsel * ((size_t)Dn * Dn / 2) + 2 * i;
        d[0] = __floats2half2_rn(v.x, v.y);
        d[1] = __floats2half2_rn(v.z, v.w);
    }
}

// ---------------- fp16 tensor-core GEMM: C[M,ldc] = A @ W^T + bias -----------
// Best config (R9/R11/R12) + spread cp.async issue: A-loads at step 0,
// B-loads at step 1, commit at step 2 (slot for kt+3 was released by the
// step-3 barrier of ktile kt-1, so early issue is race-free). Step 3 is just
// wait -> sync -> ldsm -> mma (no post-barrier load burst).
template <typename OutT>
__global__ __launch_bounds__(256, 1) void gemm_h(const __half* __restrict__ A,
                                                 const __half* __restrict__ W,
                                                 const float* __restrict__ bias,
                                                 OutT* __restrict__ C, int ldc) {
    extern __shared__ char smem[];
    const uint32_t sbase = (smem_u32(smem) + 1023u) & ~1023u;
    const int tid = threadIdx.x;
    const int wid = tid >> 5, lane = tid & 31;
    const int wm = wid >> 1, wn = wid & 1;     // warp grid 4 x 2 -> 64x64 per warp
    const int grp = lane >> 2, tg = lane & 3;
    const int m0 = blockIdx.y * BM;
    const int n0 = blockIdx.x * BN;

    const int lh = (lane >> 4) << 4;
    uint32_t baseA[4], baseB[4];
#pragma unroll
    for (int mi = 0; mi < 4; mi++) {
        int row = wm * 64 + mi * 16 + (lane & 15);
        baseA[mi] = (uint32_t)(row * ROWB) + (uint32_t)(lh ^ ((row & 7) << 4));
    }
#pragma unroll
    for (int p = 0; p < 4; p++) {
        int row = wn * 64 + p * 16 + (lane & 15);
        baseB[p] = (uint32_t)(AST + row * ROWB) + (uint32_t)(lh ^ ((row & 7) << 4));
    }

    auto load_A = [&](uint32_t stage_base, int k0) {
#pragma unroll
        for (int i = 0; i < 8; i++) {                 // A: 2048 chunks of 16B
            int c = tid + i * 256;
            int row = c >> 3, kc = c & 7;
            uint32_t off = row * ROWB + ((kc << 4) ^ ((row & 7) << 4));
            cp_async16(stage_base + off, A + (size_t)(m0 + row) * 4096 + k0 + kc * 8);
        }
    };
    auto load_B = [&](uint32_t stage_base, int k0) {
#pragma unroll
        for (int i = 0; i < 4; i++) {                 // B: 1024 chunks of 16B
            int c = tid + i * 256;
            int row = c >> 3, kc = c & 7;
            uint32_t off = AST + row * ROWB + ((kc << 4) ^ ((row & 7) << 4));
            cp_async16(stage_base + off, W + (size_t)(n0 + row) * 4096 + k0 + kc * 8);
        }
    };

    uint32_t af[2][4][4], bf[2][4][4];

    auto do_ldsm = [&](uint32_t (&ab)[4][4], uint32_t (&bb)[4][4], uint32_t sb, uint32_t stx) {
#pragma unroll
        for (int mi = 0; mi < 4; mi++) LDSM_X4(ab[mi], (sb + baseA[mi]) ^ stx);
#pragma unroll
        for (int p = 0; p < 4; p++) LDSM_X4(bb[p], (sb + baseB[p]) ^ stx);
    };

    float acc[4][8][4];
#pragma unroll
    for (int mi = 0; mi < 4; mi++)
#pragma unroll
        for (int ni = 0; ni < 8; ni++)
#pragma unroll
            for (int r = 0; r < 4; r++) acc[mi][ni][r] = 0.f;

    auto do_mma = [&](uint32_t (&ab)[4][4], uint32_t (&bb)[4][4]) {
#pragma unroll
        for (int mi = 0; mi < 4; mi++)
#pragma unroll
            for (int ni = 0; ni < 8; ni++) {
                int p = ni >> 1, hi = ni & 1;
                mma_h(acc[mi][ni], ab[mi], bb[p][hi], bb[p][hi + 2]);
            }
    };

    uint32_t stg[STG];
#pragma unroll
    for (int s = 0; s < STG; s++) stg[s] = sbase + s * STAGE_B;

    // prologue: fill 3 of 4 stages (one commit each), land stage 0
    load_A(stg[0], 0);
    load_B(stg[0], 0);
    asm volatile("cp.async.commit_group;\n" ::: "memory");
    load_A(stg[1], BKh);
    load_B(stg[1], BKh);
    asm volatile("cp.async.commit_group;\n" ::: "memory");
    load_A(stg[2], 2 * BKh);
    load_B(stg[2], 2 * BKh);
    asm volatile("cp.async.commit_group;\n" ::: "memory");
    asm volatile("cp.async.wait_group 2;\n" ::: "memory");
    __syncthreads();
    do_ldsm(af[0], bf[0], stg[0], 0);

    for (int kt = 0; kt < NKT; kt++) {
        const uint32_t scur = stg[kt & 3];
        const uint32_t snxt = stg[(kt + 1) & 3];
        const bool doload = (kt + 3 < NKT);
        const uint32_t sload = stg[(kt + 3) & 3];
        const int k0 = (kt + 3) * BKh;

        // step 0: prefetch step-1 frags; issue A loads for kt+3; MMA step 0
        do_ldsm(af[1], bf[1], scur, (uint32_t)(1 << 5));
        if (doload) load_A(sload, k0);
        do_mma(af[0], bf[0]);
        // step 1: prefetch step-2 frags; issue B loads for kt+3; MMA step 1
        do_ldsm(af[0], bf[0], scur, (uint32_t)(2 << 5));
        if (doload) load_B(sload, k0);
        do_mma(af[1], bf[1]);
        // step 2: prefetch step-3 frags; commit the kt+3 group; MMA step 2
        do_ldsm(af[1], bf[1], scur, (uint32_t)(3 << 5));
        asm volatile("cp.async.commit_group;\n" ::: "memory");
        do_mma(af[0], bf[0]);
        // step 3: wait for stage kt+1 (newest group stays in flight), barrier,
        // prefetch (kt+1, step0) frags, MMA step 3
        asm volatile("cp.async.wait_group 1;\n" ::: "memory");
        __syncthreads();
        do_ldsm(af[0], bf[0], snxt, 0);
        do_mma(af[1], bf[1]);
    }

    // epilogue: + bias
#pragma unroll
    for (int mi = 0; mi < 4; mi++) {
#pragma unroll
        for (int ni = 0; ni < 8; ni++) {
            int row = m0 + wm * 64 + mi * 16 + grp;
            int col = n0 + wn * 64 + ni * 8 + tg * 2;
            float b0 = __ldg(bias + col), b1 = __ldg(bias + col + 1);
            float c00 = acc[mi][ni][0] + b0, c01 = acc[mi][ni][1] + b1;
            float c10 = acc[mi][ni][2] + b0, c11 = acc[mi][ni][3] + b1;
            if (sizeof(OutT) == 4) {
                *(float2*)&((float*)C)[(size_t)row * ldc + col] = make_float2(c00, c01);
                *(float2*)&((float*)C)[(size_t)(row + 8) * ldc + col] = make_float2(c10, c11);
            } else {
                *(__half2*)&((__half*)C)[(size_t)row * ldc + col] = __floats2half2_rn(c00, c01);
                *(__half2*)&((__half*)C)[(size_t)(row + 8) * ldc + col] = __floats2half2_rn(c10, c11);
            }
        }
    }
}

// ---------------- stage C: vectorized attention + residual + LN --------------
__global__ void attn_ln_kernel(const __half* __restrict__ QKV, const __half* __restrict__ G16,
                               const float* __restrict__ gamma, const float* __restrict__ beta,
                               __half* __restrict__ Hout) {
    __shared__ float sscore[Hh];
    __shared__ float sw[Hh];
    __shared__ float sredA[8], sredB[8];
    __shared__ float sstat[2];

    const int b = blockIdx.x, t = threadIdx.x;
    const int warp = t >> 5, lane = t & 31;
    const size_t off12 = (size_t)b * (3 * Dn);
    const size_t off = (size_t)b * Dn;
    const float4* Qv = (const float4*)(QKV + off12);
    const float4* Kv = (const float4*)(QKV + off12 + Dn);
    const float4* Vv = (const float4*)(QKV + off12 + 2 * Dn);
    const float4* Gv = (const float4*)(G16 + off);

#pragma unroll
    for (int p = 0; p < 2; p++) {
        int idx = p * 256 + t;
        float4 q4 = Qv[idx], k4 = Kv[idx];
        const __half2* qh = (const __half2*)&q4;
        const __half2* kh = (const __half2*)&k4;
        float ps = 0.f;
#pragma unroll
        for (int j = 0; j < 4; j++) {
            float2 qf = __half22float2(qh[j]);
            float2 kf = __half22float2(kh[j]);
            ps += qf.x * kf.x + qf.y * kf.y;
        }
#pragma unroll
        for (int o = 8; o > 0; o >>= 1) ps += __shfl_down_sync(0xffffffffu, ps, o, 16);
        if ((t & 15) == 0) sscore[p * 16 + (t >> 4)] = ps;
    }
    __syncthreads();
    if (t < Hh) {
        float s = sscore[t] * 0.08838834764831845f;
        float m = s;
#pragma unroll
        for (int o = 16; o > 0; o >>= 1) m = fmaxf(m, __shfl_xor_sync(0xffffffffu, m, o));
        float e = expf(s - m);
        float sum = e;
#pragma unroll
        for (int o = 16; o > 0; o >>= 1) sum += __shfl_xor_sync(0xffffffffu, sum, o);
        sw[t] = e / sum;
    }
    __syncthreads();

    float vals[2][8];
    float s1 = 0.f, s2 = 0.f;
#pragma unroll
    for (int p = 0; p < 2; p++) {
        int idx = p * 256 + t;
        float w = sw[p * 16 + (t >> 4)];
        float4 v4 = Vv[idx], g4 = Gv[idx];
        const __half2* vh = (const __half2*)&v4;
        const __half2* gh = (const __half2*)&g4;
#pragma unroll
        for (int j = 0; j < 4; j++) {
            float2 vf = __half22float2(vh[j]);
            float2 gf = __half22float2(gh[j]);
            float a0 = w * vf.x + gf.x;
            float a1 = w * vf.y + gf.y;
            vals[p][2 * j] = a0;
            vals[p][2 * j + 1] = a1;
            s1 += a0 + a1;
            s2 += a0 * a0 + a1 * a1;
        }
    }
    s1 = warp_sum(s1);
    s2 = warp_sum(s2);
    if (lane == 0) { sredA[warp] = s1; sredB[warp] = s2; }
    __syncthreads();
    if (t == 0) {
        float S1 = 0.f, S2 = 0.f;
#pragma unroll
        for (int j = 0; j < 8; j++) { S1 += sredA[j]; S2 += sredB[j]; }
        float mean = S1 * (1.0f / Dn);
        float var = S2 * (1.0f / Dn) - mean * mean;
        sstat[0] = mean;
        sstat[1] = 1.0f / sqrtf(var + EPSf);
    }
    __syncthreads();
    const float mean = sstat[0], rstd = sstat[1];

    const float4* gmv = (const float4*)gamma;
    const float4* btv = (const float4*)beta;
#pragma unroll
    for (int p = 0; p < 2; p++) {
        int idx = p * 256 + t;
        float4 gm0 = gmv[2 * idx], gm1 = gmv[2 * idx + 1];
        float4 bt0 = btv[2 * idx], bt1 = btv[2 * idx + 1];
        float r[8];
        r[0] = (vals[p][0] - mean) * rstd * gm0.x + bt0.x;
        r[1] = (vals[p][1] - mean) * rstd * gm0.y + bt0.y;
        r[2] = (vals[p][2] - mean) * rstd * gm0.z + bt0.z;
        r[3] = (vals[p][3] - mean) * rstd * gm0.w + bt0.w;
        r[4] = (vals[p][4] - mean) * rstd * gm1.x + bt1.x;
        r[5] = (vals[p][5] - mean) * rstd * gm1.y + bt1.y;
        r[6] = (vals[p][6] - mean) * rstd * gm1.z + bt1.z;
        r[7] = (vals[p][7] - mean) * rstd * gm1.w + bt1.w;
        float4 out4;
        __half2* oh = (__half2*)&out4;
        oh[0] = __floats2half2_rn(r[0], r[1]);
        oh[1] = __floats2half2_rn(r[2], r[3]);
        oh[2] = __floats2half2_rn(r[4], r[5]);
        oh[3] = __floats2half2_rn(r[6], r[7]);
        ((float4*)(Hout + off))[idx] = out4;
    }
}

// ---------------- launch ------------------------------------------------------
extern "C" void kernel_launch(void* const* d_in, const int* in_sizes, int n_in,
                              void* d_out, int out_size) {
    const float* x = (const float*)d_in[0];
    const float* wx = (const float*)d_in[1];
    const float* wy = (const float*)d_in[3];
    const float* Wq = (const float*)d_in[5];
    const float* bq = (const float*)d_in[6];
    const float* Wk = (const float*)d_in[7];
    const float* bk = (const float*)d_in[8];
    const float* Wv = (const float*)d_in[9];
    const float* bv = (const float*)d_in[10];
    const float* Wo = (const float*)d_in[11];
    const float* bo = (const float*)d_in[12];
    const float* gamma = (const float*)d_in[13];
    const float* beta = (const float*)d_in[14];
    float* out = (float*)d_out;

    float *xm, *gx, *gy, *part, *bqkv;
    __half *g16, *h16, *qkv16, *w16;
    cudaGetSymbolAddress((void**)&g16, d_g16);
    cudaGetSymbolAddress((void**)&h16, d_h16);
    cudaGetSymbolAddress((void**)&qkv16, d_qkv16);
    cudaGetSymbolAddress((void**)&w16, d_w16);
    cudaGetSymbolAddress((void**)&bqkv, d_bqkv);
    cudaGetSymbolAddress((void**)&xm, d_xm);
    cudaGetSymbolAddress((void**)&gx, d_gx);
    cudaGetSymbolAddress((void**)&gy, d_gy);
    cudaGetSymbolAddress((void**)&part, d_part);

    __half* wo16 = w16 + 3 * (size_t)Dn * Dn;

    cudaFuncSetAttribute(gemm_h<__half>, cudaFuncAttributeMaxDynamicSharedMemorySize, SMEMB);
    cudaFuncSetAttribute(gemm_h<float>, cudaFuncAttributeMaxDynamicSharedMemorySize, SMEMB);

    // L0: row means + column partials
    rowcol_kernel<<<Bn + 2048, 128>>>(x, xm, part);
    // L1: stats + gate tables + combined bias
    statsall_kernel<<<13, 1024>>>(part, xm, wx, wy, bq, bk, bv, gx, gy, bqkv);
    // L2: gated multiply (table lookups) + weight f2h
    mega_kernel<<<2 * GMB, 256>>>(x, gx, gy, g16, (const float4*)Wq, (const float4*)Wk,
                                  (const float4*)Wv, (const float4*)Wo, (__half2*)w16);

    // L3: fused QKV GEMM (N = 12288; wq/wk/wv contiguous in w16)
    dim3 gqkv(3 * Dn / BN, Bn / BM);  // (96, 64)
    gemm_h<__half><<<gqkv, 256, SMEMB>>>(g16, w16, bqkv, qkv16, 3 * Dn);

    // L4: attention + LN (residual from g16)
    attn_ln_kernel<<<Bn, 256>>>(qkv16, g16, gamma, beta, h16);

    // L5: output GEMM (fp32 out)
    dim3 go(Dn / BN, Bn / BM);  // (32, 64)
    gemm_h<float><<<go, 256, SMEMB>>>(h16, wo16, bo, out, Dn);
}

// round 17
// speedup vs baseline: 1.4207x; 1.4207x over previous
#include <cuda_runtime.h>
#include <cuda_fp16.h>
#include <cstdint>
#include <math.h>

// Problem dims (fixed by the dataset)
#define Bn 16384
#define Dn 4096
#define Hh 32
#define HDh 128
#define EPSf 1e-5f

// ---- fp16 mma.sync GEMM tiling: 256x128 CTA tile, warp tile 64x64, occ 1 ----
#define BM 256
#define BN 128
#define BKh 64                 // K elements (fp16) per stage => 128 bytes/row
#define STG 4
#define ROWB 128               // bytes per smem row
#define AST (BM * ROWB)        // 32768
#define BST (BN * ROWB)        // 16384
#define STAGE_B (AST + BST)    // 49152
#define SMEMB (STG * STAGE_B + 1024)  // 197632
#define NKT (4096 / BKh)       // 64

// ---------------- scratch (static device allocations; no cudaMalloc) --------
__device__ __half d_g16[(size_t)Bn * Dn];
__device__ __half d_h16[(size_t)Bn * Dn];
__device__ __half d_qkv16[(size_t)Bn * 3 * Dn];
__device__ __half d_w16[4][(size_t)Dn * Dn];   // wq, wk, wv (contiguous = QKV), wo
__device__ float d_bqkv[3 * Dn];
__device__ float d_xm[Bn];
__device__ float d_ym[Dn];
__device__ float d_part[64 * Dn];
__device__ float d_stats[4];

// ---------------- helpers -----------------------------------------------------
__device__ __forceinline__ uint32_t smem_u32(const void* p) {
    uint32_t a;
    asm("{ .reg .u64 t; cvta.to.shared.u64 t, %1; cvt.u32.u64 %0, t; }" : "=r"(a) : "l"(p));
    return a;
}
__device__ __forceinline__ void cp_async16(uint32_t saddr, const void* gptr) {
    asm volatile("cp.async.cg.shared.global [%0], [%1], 16;\n" ::"r"(saddr), "l"(gptr));
}
#define LDSM_X4(r, addr)                                                         \
    asm volatile("ldmatrix.sync.aligned.m8n8.x4.shared.b16 {%0,%1,%2,%3}, [%4];" \
                 : "=r"((r)[0]), "=r"((r)[1]), "=r"((r)[2]), "=r"((r)[3])        \
                 : "r"(addr))
__device__ __forceinline__ void mma_h(float* c, const uint32_t* a, uint32_t b0, uint32_t b1) {
    asm volatile(
        "mma.sync.aligned.m16n8k16.row.col.f32.f16.f16.f32 "
        "{%0,%1,%2,%3}, {%4,%5,%6,%7}, {%8,%9}, {%0,%1,%2,%3};\n"
        : "+f"(c[0]), "+f"(c[1]), "+f"(c[2]), "+f"(c[3])
        : "r"(a[0]), "r"(a[1]), "r"(a[2]), "r"(a[3]), "r"(b0), "r"(b1));
}
__device__ __forceinline__ float warp_sum(float v) {
#pragma unroll
    for (int o = 16; o > 0; o >>= 1) v += __shfl_down_sync(0xffffffffu, v, o);
    return v;
}

// ---- L0: rowmean (blocks 0..16383, float4) + colpart (blocks 16384..) -------
__global__ void rowcol_kernel(const float* __restrict__ x, float* __restrict__ xm,
                              float* __restrict__ part) {
    __shared__ float sred[4];
    int t = threadIdx.x;
    if (blockIdx.x < Bn) {
        int b = blockIdx.x;
        const float4* xr = (const float4*)(x + (size_t)b * Dn);
        float s = 0.f;
#pragma unroll
        for (int i = 0; i < 8; i++) {
            float4 v = xr[t + i * 128];
            s += (v.x + v.y) + (v.z + v.w);
        }
        s = warp_sum(s);
        if ((t & 31) == 0) sred[t >> 5] = s;
        __syncthreads();
        if (t == 0) xm[b] = (sred[0] + sred[1] + sred[2] + sred[3]) * (1.0f / Dn);
    } else {
        int j = blockIdx.x - Bn;       // 0..2047
        int c = (j & 31) * 128 + t;    // column
        int r0 = (j >> 5) * 256;       // row chunk
        float s = 0.f;
        for (int i = 0; i < 256; i++) s += x[(size_t)(r0 + i) * Dn + c];
        part[(size_t)(j >> 5) * Dn + c] = s;
    }
}

// ---- L1: colfin (blk<32) + stats (blk 32) + combined QKV bias (blk 33..44) --
__global__ void statsall_kernel(const float* __restrict__ part, const float* __restrict__ xm,
                                const float* __restrict__ wx, const float* __restrict__ wy,
                                const float* __restrict__ bq, const float* __restrict__ bk,
                                const float* __restrict__ bv,
                                float* __restrict__ ym, float* __restrict__ stats,
                                float* __restrict__ bqkv) {
    int t = threadIdx.x;  // 1024 threads
    if (blockIdx.x < 32) {
        int c = blockIdx.x * 128 + (t & 127);
        if (t < 128) {
            float s = 0.f;
            for (int j = 0; j < 64; j++) s += part[(size_t)j * Dn + c];
            ym[c] = s * (1.0f / Bn);
        }
        return;
    }
    if (blockIdx.x > 32) {
        int i = (blockIdx.x - 33) * 1024 + t;   // 0..12287
        float v = (i < Dn) ? bq[i] : (i < 2 * Dn) ? bk[i - Dn] : bv[i - 2 * Dn];
        bqkv[i] = v;
        return;
    }
    __shared__ float sA[32], sB[32], sC[32], sD[32];
    float ys = 0.f, yss = 0.f;
    for (int c = t; c < Dn; c += 1024) {
        float s = 0.f;
        for (int j = 0; j < 64; j++) s += part[(size_t)j * Dn + c];
        float m = s * (1.0f / Bn);
        ys += m;
        yss += m * m;
    }
    float xs = 0.f, xss = 0.f;
    for (int i = t; i < Bn; i += 1024) {
        float u = xm[i];
        xs += u;
        xss += u * u;
    }
    xs = warp_sum(xs);
    xss = warp_sum(xss);
    ys = warp_sum(ys);
    yss = warp_sum(yss);
    if ((t & 31) == 0) { sA[t >> 5] = xs; sB[t >> 5] = xss; sC[t >> 5] = ys; sD[t >> 5] = yss; }
    __syncthreads();
    if (t == 0) {
        float XS = 0.f, XSS = 0.f, YS = 0.f, YSS = 0.f;
        for (int j = 0; j < 32; j++) { XS += sA[j]; XSS += sB[j]; YS += sC[j]; YSS += sD[j]; }
        float xmean = XS * (1.0f / Bn);
        float xvar = XSS * (1.0f / Bn) - xmean * xmean;
        float wxv = *wx;
        stats[0] = xmean;
        stats[1] = sqrtf(wxv * wxv * xvar + EPSf) + EPSf;
        float ymean = YS * (1.0f / Dn);
        float yvar = YSS * (1.0f / Dn) - ymean * ymean;
        float wyv = *wy;
        stats[2] = ymean;
        stats[3] = sqrtf(wyv * wyv * yvar + EPSf) + EPSf;
    }
}

// ---- L2: fused gated-multiply (blocks < GMB) + weight f2h (rest) ------------
#define GMB 65536  // gmul blocks: 16M float4 / 256
__global__ void mega_kernel(const float* __restrict__ x, const float* __restrict__ xm,
                            const float* __restrict__ ym, const float* __restrict__ stats,
                            const float* __restrict__ wxp, const float* __restrict__ wyp,
                            __half* __restrict__ g16,
                            const float4* __restrict__ w0, const float4* __restrict__ w1,
                            const float4* __restrict__ w2, const float4* __restrict__ w3,
                            __half2* __restrict__ wdst) {
    if (blockIdx.x < GMB) {
        size_t i4 = (size_t)blockIdx.x * 256 + threadIdx.x;
        int b = (int)(i4 >> 10);
        int d = (int)((i4 & 1023) << 2);
        float zx = (*wxp) * (xm[b] - stats[0]) / stats[1];
        float gxv = 1.0f / (1.0f + expf(-zx));
        float wy = *wyp, m2 = stats[2], d2 = stats[3];
        float4 xv = *(const float4*)(x + ((size_t)b << 12) + d);
        float4 gv;
        gv.x = xv.x * gxv / (1.0f + expf(-wy * (ym[d + 0] - m2) / d2));
        gv.y = xv.y * gxv / (1.0f + expf(-wy * (ym[d + 1] - m2) / d2));
        gv.z = xv.z * gxv / (1.0f + expf(-wy * (ym[d + 2] - m2) / d2));
        gv.w = xv.w * gxv / (1.0f + expf(-wy * (ym[d + 3] - m2) / d2));
        *(__half2*)(g16 + ((size_t)b << 12) + d) = __floats2half2_rn(gv.x, gv.y);
        *(__half2*)(g16 + ((size_t)b << 12) + d + 2) = __floats2half2_rn(gv.z, gv.w);
    } else {
        const float4* srcs[4] = {w0, w1, w2, w3};
        int j = blockIdx.x - GMB;          // 0..65535
        int wsel = j >> 14;                // 16384 blocks per weight
        size_t i = (size_t)(j & 16383) * 256 + threadIdx.x;
        float4 v = srcs[wsel][i];
        __half2* d = wdst + (size_t)wsel * ((size_t)Dn * Dn / 2) + 2 * i;
        d[0] = __floats2half2_rn(v.x, v.y);
        d[1] = __floats2half2_rn(v.z, v.w);
    }
}

// ---------------- fp16 tensor-core GEMM: C[M,ldc] = A @ W^T + bias -----------
// Best measured config: 256x128 CTA, warp tile 64x64 (grid 4x2), STG=4,
// frag double-buffer, step3 = wait_group 1 -> sync -> load burst -> ldsm -> mma.
template <typename OutT>
__global__ __launch_bounds__(256, 1) void gemm_h(const __half* __restrict__ A,
                                                 const __half* __restrict__ W,
                                                 const float* __restrict__ bias,
                                                 OutT* __restrict__ C, int ldc) {
    extern __shared__ char smem[];
    const uint32_t sbase = (smem_u32(smem) + 1023u) & ~1023u;
    const int tid = threadIdx.x;
    const int wid = tid >> 5, lane = tid & 31;
    const int wm = wid >> 1, wn = wid & 1;     // warp grid 4 x 2 -> 64x64 per warp
    const int grp = lane >> 2, tg = lane & 3;
    const int m0 = blockIdx.y * BM;
    const int n0 = blockIdx.x * BN;

    const int lh = (lane >> 4) << 4;
    uint32_t baseA[4], baseB[4];
#pragma unroll
    for (int mi = 0; mi < 4; mi++) {
        int row = wm * 64 + mi * 16 + (lane & 15);
        baseA[mi] = (uint32_t)(row * ROWB) + (uint32_t)(lh ^ ((row & 7) << 4));
    }
#pragma unroll
    for (int p = 0; p < 4; p++) {
        int row = wn * 64 + p * 16 + (lane & 15);
        baseB[p] = (uint32_t)(AST + row * ROWB) + (uint32_t)(lh ^ ((row & 7) << 4));
    }

    auto load_tile = [&](uint32_t stage_base, int k0) {
#pragma unroll
        for (int i = 0; i < 8; i++) {                 // A: 2048 chunks of 16B
            int c = tid + i * 256;
            int row = c >> 3, kc = c & 7;
            uint32_t off = row * ROWB + ((kc << 4) ^ ((row & 7) << 4));
            cp_async16(stage_base + off, A + (size_t)(m0 + row) * 4096 + k0 + kc * 8);
        }
#pragma unroll
        for (int i = 0; i < 4; i++) {                 // B: 1024 chunks of 16B
            int c = tid + i * 256;
            int row = c >> 3, kc = c & 7;
            uint32_t off = AST + row * ROWB + ((kc << 4) ^ ((row & 7) << 4));
            cp_async16(stage_base + off, W + (size_t)(n0 + row) * 4096 + k0 + kc * 8);
        }
        asm volatile("cp.async.commit_group;\n" ::: "memory");
    };

    uint32_t af[2][4][4], bf[2][4][4];

    auto do_ldsm = [&](uint32_t (&ab)[4][4], uint32_t (&bb)[4][4], uint32_t sb, uint32_t stx) {
#pragma unroll
        for (int mi = 0; mi < 4; mi++) LDSM_X4(ab[mi], (sb + baseA[mi]) ^ stx);
#pragma unroll
        for (int p = 0; p < 4; p++) LDSM_X4(bb[p], (sb + baseB[p]) ^ stx);
    };

    float acc[4][8][4];
#pragma unroll
    for (int mi = 0; mi < 4; mi++)
#pragma unroll
        for (int ni = 0; ni < 8; ni++)
#pragma unroll
            for (int r = 0; r < 4; r++) acc[mi][ni][r] = 0.f;

    auto do_mma = [&](uint32_t (&ab)[4][4], uint32_t (&bb)[4][4]) {
#pragma unroll
        for (int mi = 0; mi < 4; mi++)
#pragma unroll
            for (int ni = 0; ni < 8; ni++) {
                int p = ni >> 1, hi = ni & 1;
                mma_h(acc[mi][ni], ab[mi], bb[p][hi], bb[p][hi + 2]);
            }
    };

    uint32_t stg[STG];
#pragma unroll
    for (int s = 0; s < STG; s++) stg[s] = sbase + s * STAGE_B;

    load_tile(stg[0], 0);
    load_tile(stg[1], BKh);
    load_tile(stg[2], 2 * BKh);
    asm volatile("cp.async.wait_group 2;\n" ::: "memory");
    __syncthreads();
    do_ldsm(af[0], bf[0], stg[0], 0);

    for (int kt = 0; kt < NKT; kt++) {
        const uint32_t scur = stg[kt & 3];
        const uint32_t snxt = stg[(kt + 1) & 3];
#pragma unroll
        for (int step = 0; step < 3; step++) {
            const int cb = step & 1;
            do_ldsm(af[cb ^ 1], bf[cb ^ 1], scur, (uint32_t)((step + 1) << 5));
            do_mma(af[cb], bf[cb]);
        }
        asm volatile("cp.async.wait_group 1;\n" ::: "memory");
        __syncthreads();
        if (kt + 3 < NKT) load_tile(stg[(kt + 3) & 3], (kt + 3) * BKh);
        do_ldsm(af[0], bf[0], snxt, 0);
        do_mma(af[1], bf[1]);
    }

    // epilogue: + bias
#pragma unroll
    for (int mi = 0; mi < 4; mi++) {
#pragma unroll
        for (int ni = 0; ni < 8; ni++) {
            int row = m0 + wm * 64 + mi * 16 + grp;
            int col = n0 + wn * 64 + ni * 8 + tg * 2;
            float b0 = __ldg(bias + col), b1 = __ldg(bias + col + 1);
            float c00 = acc[mi][ni][0] + b0, c01 = acc[mi][ni][1] + b1;
            float c10 = acc[mi][ni][2] + b0, c11 = acc[mi][ni][3] + b1;
            if (sizeof(OutT) == 4) {
                *(float2*)&((float*)C)[(size_t)row * ldc + col] = make_float2(c00, c01);
                *(float2*)&((float*)C)[(size_t)(row + 8) * ldc + col] = make_float2(c10, c11);
            } else {
                *(__half2*)&((__half*)C)[(size_t)row * ldc + col] = __floats2half2_rn(c00, c01);
                *(__half2*)&((__half*)C)[(size_t)(row + 8) * ldc + col] = __floats2half2_rn(c10, c11);
            }
        }
    }
}

// ---------------- stage C: vectorized attention + residual + LN --------------
__global__ void attn_ln_kernel(const __half* __restrict__ QKV, const __half* __restrict__ G16,
                               const float* __restrict__ gamma, const float* __restrict__ beta,
                               __half* __restrict__ Hout) {
    __shared__ float sscore[Hh];
    __shared__ float sw[Hh];
    __shared__ float sredA[8], sredB[8];
    __shared__ float sstat[2];

    const int b = blockIdx.x, t = threadIdx.x;
    const int warp = t >> 5, lane = t & 31;
    const size_t off12 = (size_t)b * (3 * Dn);
    const size_t off = (size_t)b * Dn;
    const float4* Qv = (const float4*)(QKV + off12);
    const float4* Kv = (const float4*)(QKV + off12 + Dn);
    const float4* Vv = (const float4*)(QKV + off12 + 2 * Dn);
    const float4* Gv = (const float4*)(G16 + off);

#pragma unroll
    for (int p = 0; p < 2; p++) {
        int idx = p * 256 + t;
        float4 q4 = Qv[idx], k4 = Kv[idx];
        const __half2* qh = (const __half2*)&q4;
        const __half2* kh = (const __half2*)&k4;
        float ps = 0.f;
#pragma unroll
        for (int j = 0; j < 4; j++) {
            float2 qf = __half22float2(qh[j]);
            float2 kf = __half22float2(kh[j]);
            ps += qf.x * kf.x + qf.y * kf.y;
        }
#pragma unroll
        for (int o = 8; o > 0; o >>= 1) ps += __shfl_down_sync(0xffffffffu, ps, o, 16);
        if ((t & 15) == 0) sscore[p * 16 + (t >> 4)] = ps;
    }
    __syncthreads();
    if (t < Hh) {
        float s = sscore[t] * 0.08838834764831845f;
        float m = s;
#pragma unroll
        for (int o = 16; o > 0; o >>= 1) m = fmaxf(m, __shfl_xor_sync(0xffffffffu, m, o));
        float e = expf(s - m);
        float sum = e;
#pragma unroll
        for (int o = 16; o > 0; o >>= 1) sum += __shfl_xor_sync(0xffffffffu, sum, o);
        sw[t] = e / sum;
    }
    __syncthreads();

    float vals[2][8];
    float s1 = 0.f, s2 = 0.f;
#pragma unroll
    for (int p = 0; p < 2; p++) {
        int idx = p * 256 + t;
        float w = sw[p * 16 + (t >> 4)];
        float4 v4 = Vv[idx], g4 = Gv[idx];
        const __half2* vh = (const __half2*)&v4;
        const __half2* gh = (const __half2*)&g4;
#pragma unroll
        for (int j = 0; j < 4; j++) {
            float2 vf = __half22float2(vh[j]);
            float2 gf = __half22float2(gh[j]);
            float a0 = w * vf.x + gf.x;
            float a1 = w * vf.y + gf.y;
            vals[p][2 * j] = a0;
            vals[p][2 * j + 1] = a1;
            s1 += a0 + a1;
            s2 += a0 * a0 + a1 * a1;
        }
    }
    s1 = warp_sum(s1);
    s2 = warp_sum(s2);
    if (lane == 0) { sredA[warp] = s1; sredB[warp] = s2; }
    __syncthreads();
    if (t == 0) {
        float S1 = 0.f, S2 = 0.f;
#pragma unroll
        for (int j = 0; j < 8; j++) { S1 += sredA[j]; S2 += sredB[j]; }
        float mean = S1 * (1.0f / Dn);
        float var = S2 * (1.0f / Dn) - mean * mean;
        sstat[0] = mean;
        sstat[1] = 1.0f / sqrtf(var + EPSf);
    }
    __syncthreads();
    const float mean = sstat[0], rstd = sstat[1];

    const float4* gmv = (const float4*)gamma;
    const float4* btv = (const float4*)beta;
#pragma unroll
    for (int p = 0; p < 2; p++) {
        int idx = p * 256 + t;
        float4 gm0 = gmv[2 * idx], gm1 = gmv[2 * idx + 1];
        float4 bt0 = btv[2 * idx], bt1 = btv[2 * idx + 1];
        float r[8];
        r[0] = (vals[p][0] - mean) * rstd * gm0.x + bt0.x;
        r[1] = (vals[p][1] - mean) * rstd * gm0.y + bt0.y;
        r[2] = (vals[p][2] - mean) * rstd * gm0.z + bt0.z;
        r[3] = (vals[p][3] - mean) * rstd * gm0.w + bt0.w;
        r[4] = (vals[p][4] - mean) * rstd * gm1.x + bt1.x;
        r[5] = (vals[p][5] - mean) * rstd * gm1.y + bt1.y;
        r[6] = (vals[p][6] - mean) * rstd * gm1.z + bt1.z;
        r[7] = (vals[p][7] - mean) * rstd * gm1.w + bt1.w;
        float4 out4;
        __half2* oh = (__half2*)&out4;
        oh[0] = __floats2half2_rn(r[0], r[1]);
        oh[1] = __floats2half2_rn(r[2], r[3]);
        oh[2] = __floats2half2_rn(r[4], r[5]);
        oh[3] = __floats2half2_rn(r[6], r[7]);
        ((float4*)(Hout + off))[idx] = out4;
    }
}

// ---------------- launch ------------------------------------------------------
extern "C" void kernel_launch(void* const* d_in, const int* in_sizes, int n_in,
                              void* d_out, int out_size) {
    const float* x = (const float*)d_in[0];
    const float* wx = (const float*)d_in[1];
    const float* wy = (const float*)d_in[3];
    const float* Wq = (const float*)d_in[5];
    const float* bq = (const float*)d_in[6];
    const float* Wk = (const float*)d_in[7];
    const float* bk = (const float*)d_in[8];
    const float* Wv = (const float*)d_in[9];
    const float* bv = (const float*)d_in[10];
    const float* Wo = (const float*)d_in[11];
    const float* bo = (const float*)d_in[12];
    const float* gamma = (const float*)d_in[13];
    const float* beta = (const float*)d_in[14];
    float* out = (float*)d_out;

    float *xm, *ym, *part, *stats, *bqkv;
    __half *g16, *h16, *qkv16, *w16;
    cudaGetSymbolAddress((void**)&g16, d_g16);
    cudaGetSymbolAddress((void**)&h16, d_h16);
    cudaGetSymbolAddress((void**)&qkv16, d_qkv16);
    cudaGetSymbolAddress((void**)&w16, d_w16);
    cudaGetSymbolAddress((void**)&bqkv, d_bqkv);
    cudaGetSymbolAddress((void**)&xm, d_xm);
    cudaGetSymbolAddress((void**)&ym, d_ym);
    cudaGetSymbolAddress((void**)&part, d_part);
    cudaGetSymbolAddress((void**)&stats, d_stats);

    __half* wo16 = w16 + 3 * (size_t)Dn * Dn;

    cudaFuncSetAttribute(gemm_h<__half>, cudaFuncAttributeMaxDynamicSharedMemorySize, SMEMB);
    cudaFuncSetAttribute(gemm_h<float>, cudaFuncAttributeMaxDynamicSharedMemorySize, SMEMB);

    // L0: row means + column partials
    rowcol_kernel<<<Bn + 2048, 128>>>(x, xm, part);
    // L1: column means + stats + combined bias
    statsall_kernel<<<45, 1024>>>(part, xm, wx, wy, bq, bk, bv, ym, stats, bqkv);
    // L2: gated multiply + weight f2h
    mega_kernel<<<2 * GMB, 256>>>(x, xm, ym, stats, wx, wy, g16,
                                  (const float4*)Wq, (const float4*)Wk, (const float4*)Wv,
                                  (const float4*)Wo, (__half2*)w16);

    // L3: fused QKV GEMM (N = 12288; wq/wk/wv contiguous in w16)
    dim3 gqkv(3 * Dn / BN, Bn / BM);  // (96, 64)
    gemm_h<__half><<<gqkv, 256, SMEMB>>>(g16, w16, bqkv, qkv16, 3 * Dn);

    // L4: attention + LN (residual from g16)
    attn_ln_kernel<<<Bn, 256>>>(qkv16, g16, gamma, beta, h16);

    // L5: output GEMM (fp32 out)
    dim3 go(Dn / BN, Bn / BM);  // (32, 64)
    gemm_h<float><<<go, 256, SMEMB>>>(h16, wo16, bo, out, Dn);
}